// round 1
// baseline (speedup 1.0000x reference)
#include <cuda_runtime.h>
#include <cuda_bf16.h>

#define SEQ   2048
#define BATCH 32
#define DIM   256
#define HEADS 4
#define MROWS (SEQ*BATCH)      /* 65536 */
#define NBUF  (MROWS*DIM)      /* 16777216 floats = 64MB */

// Scratch: Q ping/pong, K ping/pong, V ping/pong, W ping/pong  (8 x 64MB)
__device__ float g_buf[8][NBUF];
__device__ float g_stats[2*DIM];
__device__ float g_bnscale[DIM];
__device__ float g_bnshift[DIM];
__device__ float g_headout[HEADS*BATCH*DIM];
__device__ float g_x0[BATCH*HEADS*DIM];
__device__ float g_x1[BATCH*DIM];
__device__ float g_x2[BATCH*DIM];

__device__ __forceinline__ unsigned long long ffma2(unsigned long long a,
                                                    unsigned long long b,
                                                    unsigned long long c) {
    unsigned long long d;
    asm("fma.rn.f32x2 %0, %1, %2, %3;" : "=l"(d) : "l"(a), "l"(b), "l"(c));
    return d;
}

// ---------------------------------------------------------------------------
// C[M,256] = op(A)[M,256] @ W[256,256]^T + bias
//   op(A) = A                              (BNRELU=false)
//   op(A) = relu(A*bnsc[k] + bnsh[k])      (BNRELU=true, per-K-channel)
// Tile 128x128x16, 256 threads, 8x8 per thread, FFMA2 inner loop.
// A tile stored DUPLICATED in SMEM: AsD[k][2m]=AsD[k][2m+1]=A[m][k] so that a
// single LDS.128 yields two packed (a,a) f32x2 operands.
// ---------------------------------------------------------------------------
template<bool BNRELU>
__global__ __launch_bounds__(256, 2)
void gemm_kernel(const float* __restrict__ A, const float* __restrict__ W,
                 const float* __restrict__ bias,
                 const float* __restrict__ bnsc, const float* __restrict__ bnsh,
                 float* __restrict__ C)
{
    constexpr int BM = 128, BN = 128, BK = 16;
    __shared__ float AsD[BK][2*BM];
    __shared__ float Bs[BK][BN];

    const int tid = threadIdx.x;
    const int tx  = tid & 15;
    const int ty  = tid >> 4;
    const int n0  = tx * 8;
    const int m0  = ty * 8;
    const int blockN = blockIdx.x * BN;
    const int blockM = blockIdx.y * BM;

    const int lrow = tid >> 2;        // 0..63
    const int lk   = (tid & 3) << 2;  // 0,4,8,12

    unsigned long long acc[8][4];
    #pragma unroll
    for (int i = 0; i < 8; i++)
        #pragma unroll
        for (int j = 0; j < 4; j++) acc[i][j] = 0ull;

    #pragma unroll 1
    for (int kt = 0; kt < DIM; kt += BK) {
        float4 sc, sh;
        if (BNRELU) {
            sc = *(const float4*)&bnsc[kt + lk];
            sh = *(const float4*)&bnsh[kt + lk];
        }
        #pragma unroll
        for (int r = 0; r < 128; r += 64) {
            float4 a = *(const float4*)&A[(blockM + lrow + r) * DIM + kt + lk];
            if (BNRELU) {
                a.x = fmaxf(fmaf(a.x, sc.x, sh.x), 0.f);
                a.y = fmaxf(fmaf(a.y, sc.y, sh.y), 0.f);
                a.z = fmaxf(fmaf(a.z, sc.z, sh.z), 0.f);
                a.w = fmaxf(fmaf(a.w, sc.w, sh.w), 0.f);
            }
            const int mm = 2 * (lrow + r);
            *(float2*)&AsD[lk + 0][mm] = make_float2(a.x, a.x);
            *(float2*)&AsD[lk + 1][mm] = make_float2(a.y, a.y);
            *(float2*)&AsD[lk + 2][mm] = make_float2(a.z, a.z);
            *(float2*)&AsD[lk + 3][mm] = make_float2(a.w, a.w);

            float4 b = *(const float4*)&W[(blockN + lrow + r) * DIM + kt + lk];
            Bs[lk + 0][lrow + r] = b.x;
            Bs[lk + 1][lrow + r] = b.y;
            Bs[lk + 2][lrow + r] = b.z;
            Bs[lk + 3][lrow + r] = b.w;
        }
        __syncthreads();
        #pragma unroll
        for (int k = 0; k < BK; k++) {
            ulonglong2 a01 = *(const ulonglong2*)&AsD[k][2*m0];
            ulonglong2 a23 = *(const ulonglong2*)&AsD[k][2*m0 + 4];
            ulonglong2 a45 = *(const ulonglong2*)&AsD[k][2*m0 + 8];
            ulonglong2 a67 = *(const ulonglong2*)&AsD[k][2*m0 + 12];
            ulonglong2 b03 = *(const ulonglong2*)&Bs[k][n0];
            ulonglong2 b47 = *(const ulonglong2*)&Bs[k][n0 + 4];
            unsigned long long ra[8] = {a01.x, a01.y, a23.x, a23.y,
                                        a45.x, a45.y, a67.x, a67.y};
            unsigned long long rb[4] = {b03.x, b03.y, b47.x, b47.y};
            #pragma unroll
            for (int mi = 0; mi < 8; mi++)
                #pragma unroll
                for (int p = 0; p < 4; p++)
                    acc[mi][p] = ffma2(ra[mi], rb[p], acc[mi][p]);
        }
        __syncthreads();
    }

    float4 b0 = *(const float4*)&bias[blockN + n0];
    float4 b1 = *(const float4*)&bias[blockN + n0 + 4];
    #pragma unroll
    for (int mi = 0; mi < 8; mi++) {
        union { unsigned long long u; float2 f; } c0, c1, c2, c3;
        c0.u = acc[mi][0]; c1.u = acc[mi][1]; c2.u = acc[mi][2]; c3.u = acc[mi][3];
        float4 o0 = make_float4(c0.f.x + b0.x, c0.f.y + b0.y,
                                c1.f.x + b0.z, c1.f.y + b0.w);
        float4 o1 = make_float4(c2.f.x + b1.x, c2.f.y + b1.y,
                                c3.f.x + b1.z, c3.f.y + b1.w);
        float* cp = &C[(blockM + m0 + mi) * DIM + blockN + n0];
        *(float4*)cp       = o0;
        *(float4*)(cp + 4) = o1;
    }
}

// ---------------------------------------------------------------------------
__global__ void zero_stats_kernel(float* __restrict__ s) { s[threadIdx.x] = 0.f; }

// W = K - Q, plus per-channel sum / sumsq  (thread = channel, block strides rows)
__global__ void sub_stats_kernel(const float* __restrict__ Kx, const float* __restrict__ Qx,
                                 float* __restrict__ Wout, float* __restrict__ stats)
{
    const int d = threadIdx.x;
    float s1 = 0.f, s2 = 0.f;
    for (int r = blockIdx.x; r < MROWS; r += gridDim.x) {
        const int i = r * DIM + d;
        float w = Kx[i] - Qx[i];
        Wout[i] = w;
        s1 += w; s2 += w * w;
    }
    atomicAdd(&stats[d], s1);
    atomicAdd(&stats[DIM + d], s2);
}

__global__ void stats_kernel(const float* __restrict__ X, float* __restrict__ stats)
{
    const int d = threadIdx.x;
    float s1 = 0.f, s2 = 0.f;
    for (int r = blockIdx.x; r < MROWS; r += gridDim.x) {
        float w = X[r * DIM + d];
        s1 += w; s2 += w * w;
    }
    atomicAdd(&stats[d], s1);
    atomicAdd(&stats[DIM + d], s2);
}

__global__ void bn_finalize_kernel(const float* __restrict__ stats,
                                   const float* __restrict__ gamma,
                                   const float* __restrict__ beta,
                                   float* __restrict__ sc, float* __restrict__ sh)
{
    const int d = threadIdx.x;
    const float inv = 1.f / (float)MROWS;
    float mean = stats[d] * inv;
    float var  = stats[DIM + d] * inv - mean * mean;
    float r    = rsqrtf(var + 1e-5f);
    float s    = gamma[d] * r;
    sc[d] = s;
    sh[d] = beta[d] - mean * s;
}

// ---------------------------------------------------------------------------
// Fused softmax(axis=0) + sum_s(p * v). One block per (b, 32 d-columns).
// lanes span d (coalesced 128B), 8 warps split S; online softmax, then
// cross-warp merge of (m, Z, acc) in shared memory.
// ---------------------------------------------------------------------------
__global__ void softmax_wsum_kernel(const float* __restrict__ Wm,
                                    const float* __restrict__ V,
                                    float* __restrict__ out)
{
    const int b    = blockIdx.x >> 3;
    const int lane = threadIdx.x & 31;
    const int w    = threadIdx.x >> 5;
    const int d    = ((blockIdx.x & 7) << 5) + lane;
    const int BD   = BATCH * DIM;
    const int base = b * DIM + d;

    const float NEG_INF = __int_as_float(0xff800000u);
    float m = NEG_INF, Z = 0.f, acc = 0.f;
    const int s0 = w * (SEQ / 8);
    for (int s = s0; s < s0 + SEQ / 8; s++) {
        const int idx = s * BD + base;
        float x  = Wm[idx];
        float vv = V[idx];
        if (x > m) {
            float c = __expf(m - x);
            Z   = Z * c + 1.f;
            acc = acc * c + vv;
            m = x;
        } else {
            float e = __expf(x - m);
            Z   += e;
            acc += e * vv;
        }
    }
    __shared__ float sm[8][32], sz[8][32], sa[8][32];
    sm[w][lane] = m; sz[w][lane] = Z; sa[w][lane] = acc;
    __syncthreads();
    if (w == 0) {
        float M = NEG_INF;
        #pragma unroll
        for (int j = 0; j < 8; j++) M = fmaxf(M, sm[j][lane]);
        float Zt = 0.f, At = 0.f;
        #pragma unroll
        for (int j = 0; j < 8; j++) {
            float c = __expf(sm[j][lane] - M);
            Zt += sz[j][lane] * c;
            At += sa[j][lane] * c;
        }
        out[base] = At / Zt;
    }
}

// concat heads: x0[b, h*256+d] = headout[h][b][d]
__global__ void pack_kernel(const float* __restrict__ ho, float* __restrict__ x0)
{
    const int i = blockIdx.x * blockDim.x + threadIdx.x;
    const int b = i >> 10;
    const int c = i & 1023;
    const int h = c >> 8;
    const int d = c & 255;
    x0[i] = ho[h * (BATCH * DIM) + b * DIM + d];
}

// C[32,256] = act(X[32,K] @ Wt[256,K]^T + bias). Tiny; staged in SMEM.
template<bool RELU, int K>
__global__ void smallgemm_kernel(const float* __restrict__ X, const float* __restrict__ Wt,
                                 const float* __restrict__ bias, float* __restrict__ C)
{
    __shared__ float Xs[32][257];
    __shared__ float Ws[8][257];
    const int tid = threadIdx.x;
    const int b  = tid & 31;
    const int nl = tid >> 5;
    const int n  = blockIdx.x * 8 + nl;
    float acc = 0.f;
    for (int k0 = 0; k0 < K; k0 += 256) {
        #pragma unroll
        for (int j = 0; j < 8; j++)
            Ws[j][tid] = Wt[(blockIdx.x * 8 + j) * K + k0 + tid];
        #pragma unroll
        for (int j = 0; j < 32; j++)
            Xs[j][tid] = X[j * K + k0 + tid];
        __syncthreads();
        #pragma unroll 8
        for (int kk = 0; kk < 256; kk++) acc += Xs[b][kk] * Ws[nl][kk];
        __syncthreads();
    }
    float val = acc + bias[n];
    if (RELU) val = fmaxf(val, 0.f);
    C[b * DIM + n] = val;
}

// ---------------------------------------------------------------------------
extern "C" void kernel_launch(void* const* d_in, const int* in_sizes, int n_in,
                              void* d_out, int out_size)
{
    const float* q   = (const float*)d_in[0];
    const float* k   = (const float*)d_in[1];
    const float* v   = (const float*)d_in[2];
    const float* wq  = (const float*)d_in[3];
    const float* bq  = (const float*)d_in[4];
    const float* wk  = (const float*)d_in[5];
    const float* bk  = (const float*)d_in[6];
    const float* wv  = (const float*)d_in[7];
    const float* bv  = (const float*)d_in[8];
    const float* g1  = (const float*)d_in[9];
    const float* be1 = (const float*)d_in[10];
    const float* wl1 = (const float*)d_in[11];
    const float* bl1 = (const float*)d_in[12];
    const float* g2  = (const float*)d_in[13];
    const float* be2 = (const float*)d_in[14];
    const float* wl2 = (const float*)d_in[15];
    const float* bl2 = (const float*)d_in[16];
    const float* mw0 = (const float*)d_in[17];
    const float* mb0 = (const float*)d_in[18];
    const float* mw1 = (const float*)d_in[19];
    const float* mb1 = (const float*)d_in[20];
    const float* mw2 = (const float*)d_in[21];
    const float* mb2 = (const float*)d_in[22];

    float* buf;   cudaGetSymbolAddress((void**)&buf,   g_buf);
    float* stats; cudaGetSymbolAddress((void**)&stats, g_stats);
    float* bnsc;  cudaGetSymbolAddress((void**)&bnsc,  g_bnscale);
    float* bnsh;  cudaGetSymbolAddress((void**)&bnsh,  g_bnshift);
    float* ho;    cudaGetSymbolAddress((void**)&ho,    g_headout);
    float* x0;    cudaGetSymbolAddress((void**)&x0,    g_x0);
    float* x1;    cudaGetSymbolAddress((void**)&x1,    g_x1);
    float* x2;    cudaGetSymbolAddress((void**)&x2,    g_x2);

    float* Qb[2] = { buf + (size_t)0*NBUF, buf + (size_t)1*NBUF };
    float* Kb[2] = { buf + (size_t)2*NBUF, buf + (size_t)3*NBUF };
    float* Vb[2] = { buf + (size_t)4*NBUF, buf + (size_t)5*NBUF };
    float* Wa    =   buf + (size_t)6*NBUF;
    float* Wb    =   buf + (size_t)7*NBUF;

    dim3 gg(DIM / 128, MROWS / 128);   // (2, 512)

    const float* Qc = q; const float* Kc = k; const float* Vc = v;
    for (int i = 0; i < HEADS; i++) {
        float* Qn = Qb[i & 1]; float* Kn = Kb[i & 1]; float* Vn = Vb[i & 1];

        gemm_kernel<false><<<gg, 256>>>(Qc, wq + i*DIM*DIM, bq + i*DIM, nullptr, nullptr, Qn);
        gemm_kernel<false><<<gg, 256>>>(Kc, wk + i*DIM*DIM, bk + i*DIM, nullptr, nullptr, Kn);
        gemm_kernel<false><<<gg, 256>>>(Vc, wv + i*DIM*DIM, bv + i*DIM, nullptr, nullptr, Vn);

        zero_stats_kernel<<<1, 2*DIM>>>(stats);
        sub_stats_kernel<<<2048, DIM>>>(Kn, Qn, Wa, stats);
        bn_finalize_kernel<<<1, DIM>>>(stats, g1 + i*DIM, be1 + i*DIM, bnsc, bnsh);

        gemm_kernel<true><<<gg, 256>>>(Wa, wl1 + i*DIM*DIM, bl1 + i*DIM, bnsc, bnsh, Wb);

        zero_stats_kernel<<<1, 2*DIM>>>(stats);
        stats_kernel<<<2048, DIM>>>(Wb, stats);
        bn_finalize_kernel<<<1, DIM>>>(stats, g2 + i*DIM, be2 + i*DIM, bnsc, bnsh);

        gemm_kernel<true><<<gg, 256>>>(Wb, wl2 + i*DIM*DIM, bl2 + i*DIM, bnsc, bnsh, Wa);

        softmax_wsum_kernel<<<BATCH * (DIM / 32), 256>>>(Wa, Vn, ho + i*BATCH*DIM);

        Qc = Qn; Kc = Kn; Vc = Vn;
    }

    pack_kernel<<<32, 1024>>>(ho, x0);
    smallgemm_kernel<true,  HEADS*DIM><<<DIM / 8, 256>>>(x0, mw0, mb0, x1);
    smallgemm_kernel<true,  DIM      ><<<DIM / 8, 256>>>(x1, mw1, mb1, x2);
    smallgemm_kernel<false, DIM      ><<<DIM / 8, 256>>>(x2, mw2, mb2, (float*)d_out);
}

// round 3
// speedup vs baseline: 2.6019x; 2.6019x over previous
#include <cuda_runtime.h>
#include <cuda_bf16.h>
#include <cstdint>

#define SEQ   2048
#define BATCH 32
#define DIM   256
#define HEADS 4
#define MROWS (SEQ*BATCH)      /* 65536 */
#define NBUF  (MROWS*DIM)      /* 16777216 floats = 64MB */

__device__ float g_buf[8][NBUF];
__device__ float g_stats[2*DIM];
__device__ float g_bnscale[DIM];
__device__ float g_bnshift[DIM];
__device__ float g_headout[HEADS*BATCH*DIM];
__device__ float g_x0[BATCH*HEADS*DIM];
__device__ float g_x1[BATCH*DIM];
__device__ float g_x2[BATCH*DIM];

// ===========================================================================
// helpers
// ===========================================================================
__device__ __forceinline__ uint32_t smem_u32(const void* p) {
    uint32_t a;
    asm("{ .reg .u64 t; cvta.to.shared.u64 t, %1; cvt.u32.u64 %0, t; }" : "=r"(a) : "l"(p));
    return a;
}
__device__ __forceinline__ void ldsm4(uint32_t* r, uint32_t addr) {
    asm volatile("ldmatrix.sync.aligned.m8n8.x4.shared.b16 {%0,%1,%2,%3}, [%4];"
                 : "=r"(r[0]), "=r"(r[1]), "=r"(r[2]), "=r"(r[3]) : "r"(addr));
}
__device__ __forceinline__ void mma_bf16(float* c, const uint32_t* a, uint32_t b0, uint32_t b1) {
    asm volatile("mma.sync.aligned.m16n8k16.row.col.f32.bf16.bf16.f32 "
                 "{%0,%1,%2,%3}, {%4,%5,%6,%7}, {%8,%9}, {%0,%1,%2,%3};"
                 : "+f"(c[0]), "+f"(c[1]), "+f"(c[2]), "+f"(c[3])
                 : "r"(a[0]), "r"(a[1]), "r"(a[2]), "r"(a[3]), "r"(b0), "r"(b1));
}
__device__ __forceinline__ uint32_t pack_bf16(float x, float y) {
    __nv_bfloat162 t = __floats2bfloat162_rn(x, y);
    return *(uint32_t*)&t;
}
// split f into hi (bf16) + lo (bf16 of residual)
__device__ __forceinline__ void split_bf16(float f, float& hi, float& lo) {
    __nv_bfloat16 bh = __float2bfloat16_rn(f);
    hi = __bfloat162float(bh);
    lo = f - hi;
}

// ===========================================================================
// bf16-split tensor-core GEMM: C[M,256] = op(A)[M,256] @ W[256,256]^T + bias
//   op(A)=A (BNRELU=false) | relu(A*bnsc[k]+bnsh[k]) (BNRELU=true)
// CTA 128x128, 8 warps (2M x 4N), warp 64x32, BK=16, double-buffered SMEM.
// Panels per stage (row stride 48B, conflict-free for ldmatrix):
//   Ah +0, Al +6144, Bh +12288, Bl +18432 ; stage size 24576, 2 stages = 48KB.
// ===========================================================================
#define STAGE_B 24576

template<bool BNRELU>
__global__ __launch_bounds__(256, 2)
void mma_gemm_kernel(const float* __restrict__ A, const float* __restrict__ W,
                     const float* __restrict__ bias,
                     const float* __restrict__ bnsc, const float* __restrict__ bnsh,
                     float* __restrict__ C)
{
    __shared__ char smem[2 * STAGE_B];
    const uint32_t sb = smem_u32(smem);

    const int tid  = threadIdx.x;
    const int lane = tid & 31;
    const int wid  = tid >> 5;
    const int warpM = wid >> 2;          // 0..1  -> 64 rows
    const int warpN = wid & 3;           // 0..3  -> 32 cols
    const int blockN = blockIdx.x * 128;
    const int blockM = blockIdx.y * 128;

    // ldmatrix source offsets (within a panel)
    const uint32_t aoff = (uint32_t)((warpM * 64 + (lane & 15)) * 48 + (lane >> 4) * 16);
    const uint32_t boff = (uint32_t)((warpN * 32 + (lane & 7) + ((lane >> 4) & 1) * 8) * 48
                                     + ((lane >> 3) & 1) * 16);

    // producer mapping: idx = tid + j*256 -> row = idx>>2 (0..127), q = idx&3
    const int prow = tid >> 2;
    const int pq   = tid & 3;

    float acc[4][4][4];
    #pragma unroll
    for (int i = 0; i < 4; i++)
        #pragma unroll
        for (int j = 0; j < 4; j++)
            #pragma unroll
            for (int r = 0; r < 4; r++) acc[i][j][r] = 0.f;

    // ---- producer: convert one float4 into h/l bf16 pairs and store ----
    auto stsplit = [&](uint32_t panel_h, uint32_t soff, float4 a) {
        float h0,l0,h1,l1,h2,l2,h3,l3;
        split_bf16(a.x, h0, l0); split_bf16(a.y, h1, l1);
        split_bf16(a.z, h2, l2); split_bf16(a.w, h3, l3);
        uint32_t hh[2] = { pack_bf16(h0, h1), pack_bf16(h2, h3) };
        uint32_t ll[2] = { pack_bf16(l0, l1), pack_bf16(l2, l3) };
        *(uint2*)(smem + panel_h + soff)        = make_uint2(hh[0], hh[1]);
        *(uint2*)(smem + panel_h + 6144 + soff) = make_uint2(ll[0], ll[1]);
    };

    // prologue: fill stage 0 (kt = 0)
    {
        #pragma unroll
        for (int j = 0; j < 2; j++) {
            const int row = prow + j * 64;
            const uint32_t soff = (uint32_t)(row * 48 + pq * 8);
            float4 a = *(const float4*)&A[(blockM + row) * DIM + pq * 4];
            if (BNRELU) {
                const float4 sc = *(const float4*)&bnsc[pq * 4];
                const float4 sh = *(const float4*)&bnsh[pq * 4];
                a.x = fmaxf(fmaf(a.x, sc.x, sh.x), 0.f);
                a.y = fmaxf(fmaf(a.y, sc.y, sh.y), 0.f);
                a.z = fmaxf(fmaf(a.z, sc.z, sh.z), 0.f);
                a.w = fmaxf(fmaf(a.w, sc.w, sh.w), 0.f);
            }
            stsplit(0, soff, a);
            float4 b = *(const float4*)&W[(blockN + row) * DIM + pq * 4];
            stsplit(12288, soff, b);
        }
    }
    __syncthreads();

    #pragma unroll 1
    for (int ks = 0; ks < 16; ks++) {
        const uint32_t cur = (uint32_t)(ks & 1) * STAGE_B;
        const uint32_t nxt = (uint32_t)((ks + 1) & 1) * STAGE_B;

        // ---- issue next-stage global loads early ----
        float4 gA[2], gB[2];
        if (ks < 15) {
            const int kt = (ks + 1) * 16;
            #pragma unroll
            for (int j = 0; j < 2; j++) {
                const int row = prow + j * 64;
                gA[j] = *(const float4*)&A[(blockM + row) * DIM + kt + pq * 4];
                gB[j] = *(const float4*)&W[(blockN + row) * DIM + kt + pq * 4];
            }
        }

        // ---- compute current stage: 3 split terms ----
        {
            uint32_t bh[4][2];
            #pragma unroll
            for (int j = 0; j < 2; j++) {
                uint32_t t[4];
                ldsm4(t, sb + cur + 12288 + boff + (uint32_t)(j * 768));
                bh[2*j][0] = t[0]; bh[2*j][1] = t[1];
                bh[2*j+1][0] = t[2]; bh[2*j+1][1] = t[3];
            }
            uint32_t af[4][4];
            #pragma unroll
            for (int mt = 0; mt < 4; mt++)
                ldsm4(af[mt], sb + cur + aoff + (uint32_t)(mt * 768));
            #pragma unroll
            for (int mt = 0; mt < 4; mt++)
                #pragma unroll
                for (int nt = 0; nt < 4; nt++)
                    mma_bf16(acc[mt][nt], af[mt], bh[nt][0], bh[nt][1]);   // ah*bh

            uint32_t blq[4][2];
            #pragma unroll
            for (int j = 0; j < 2; j++) {
                uint32_t t[4];
                ldsm4(t, sb + cur + 18432 + boff + (uint32_t)(j * 768));
                blq[2*j][0] = t[0]; blq[2*j][1] = t[1];
                blq[2*j+1][0] = t[2]; blq[2*j+1][1] = t[3];
            }
            #pragma unroll
            for (int mt = 0; mt < 4; mt++)
                #pragma unroll
                for (int nt = 0; nt < 4; nt++)
                    mma_bf16(acc[mt][nt], af[mt], blq[nt][0], blq[nt][1]); // ah*bl

            #pragma unroll
            for (int mt = 0; mt < 4; mt++)
                ldsm4(af[mt], sb + cur + 6144 + aoff + (uint32_t)(mt * 768));
            #pragma unroll
            for (int mt = 0; mt < 4; mt++)
                #pragma unroll
                for (int nt = 0; nt < 4; nt++)
                    mma_bf16(acc[mt][nt], af[mt], bh[nt][0], bh[nt][1]);   // al*bh
        }

        // ---- convert + store next stage ----
        if (ks < 15) {
            const int kt = (ks + 1) * 16;
            #pragma unroll
            for (int j = 0; j < 2; j++) {
                const int row = prow + j * 64;
                const uint32_t soff = (uint32_t)(row * 48 + pq * 8);
                float4 a = gA[j];
                if (BNRELU) {
                    const float4 sc = *(const float4*)&bnsc[kt + pq * 4];
                    const float4 sh = *(const float4*)&bnsh[kt + pq * 4];
                    a.x = fmaxf(fmaf(a.x, sc.x, sh.x), 0.f);
                    a.y = fmaxf(fmaf(a.y, sc.y, sh.y), 0.f);
                    a.z = fmaxf(fmaf(a.z, sc.z, sh.z), 0.f);
                    a.w = fmaxf(fmaf(a.w, sc.w, sh.w), 0.f);
                }
                stsplit(nxt, soff, a);
                stsplit(nxt + 12288, soff, gB[j]);
            }
        }
        __syncthreads();
    }

    // ---- epilogue: bias add + direct stores ----
    #pragma unroll
    for (int nt = 0; nt < 4; nt++) {
        const int n0 = blockN + warpN * 32 + nt * 8 + (lane & 3) * 2;
        const float2 bb = *(const float2*)&bias[n0];
        #pragma unroll
        for (int mt = 0; mt < 4; mt++) {
            const int m0 = blockM + warpM * 64 + mt * 16 + (lane >> 2);
            float2 o0 = make_float2(acc[mt][nt][0] + bb.x, acc[mt][nt][1] + bb.y);
            float2 o1 = make_float2(acc[mt][nt][2] + bb.x, acc[mt][nt][3] + bb.y);
            *(float2*)&C[m0 * DIM + n0]       = o0;
            *(float2*)&C[(m0 + 8) * DIM + n0] = o1;
        }
    }
}

// ---------------------------------------------------------------------------
__global__ void zero_stats_kernel(float* __restrict__ s) { s[threadIdx.x] = 0.f; }

__global__ void sub_stats_kernel(const float* __restrict__ Kx, const float* __restrict__ Qx,
                                 float* __restrict__ Wout, float* __restrict__ stats)
{
    const int d = threadIdx.x;
    float s1 = 0.f, s2 = 0.f;
    for (int r = blockIdx.x; r < MROWS; r += gridDim.x) {
        const int i = r * DIM + d;
        float w = Kx[i] - Qx[i];
        Wout[i] = w;
        s1 += w; s2 += w * w;
    }
    atomicAdd(&stats[d], s1);
    atomicAdd(&stats[DIM + d], s2);
}

__global__ void stats_kernel(const float* __restrict__ X, float* __restrict__ stats)
{
    const int d = threadIdx.x;
    float s1 = 0.f, s2 = 0.f;
    for (int r = blockIdx.x; r < MROWS; r += gridDim.x) {
        float w = X[r * DIM + d];
        s1 += w; s2 += w * w;
    }
    atomicAdd(&stats[d], s1);
    atomicAdd(&stats[DIM + d], s2);
}

__global__ void bn_finalize_kernel(const float* __restrict__ stats,
                                   const float* __restrict__ gamma,
                                   const float* __restrict__ beta,
                                   float* __restrict__ sc, float* __restrict__ sh)
{
    const int d = threadIdx.x;
    const float inv = 1.f / (float)MROWS;
    float mean = stats[d] * inv;
    float var  = stats[DIM + d] * inv - mean * mean;
    float r    = rsqrtf(var + 1e-5f);
    float s    = gamma[d] * r;
    sc[d] = s;
    sh[d] = beta[d] - mean * s;
}

// ---------------------------------------------------------------------------
__global__ void softmax_wsum_kernel(const float* __restrict__ Wm,
                                    const float* __restrict__ V,
                                    float* __restrict__ out)
{
    const int b    = blockIdx.x >> 3;
    const int lane = threadIdx.x & 31;
    const int w    = threadIdx.x >> 5;
    const int d    = ((blockIdx.x & 7) << 5) + lane;
    const int BD   = BATCH * DIM;
    const int base = b * DIM + d;

    const float NEG_INF = __int_as_float(0xff800000u);
    float m = NEG_INF, Z = 0.f, acc = 0.f;
    const int s0 = w * (SEQ / 8);
    for (int s = s0; s < s0 + SEQ / 8; s++) {
        const int idx = s * BD + base;
        float x  = Wm[idx];
        float vv = V[idx];
        if (x > m) {
            float c = __expf(m - x);
            Z   = Z * c + 1.f;
            acc = acc * c + vv;
            m = x;
        } else {
            float e = __expf(x - m);
            Z   += e;
            acc += e * vv;
        }
    }
    __shared__ float sm[8][32], sz[8][32], sa[8][32];
    sm[w][lane] = m; sz[w][lane] = Z; sa[w][lane] = acc;
    __syncthreads();
    if (w == 0) {
        float M = NEG_INF;
        #pragma unroll
        for (int j = 0; j < 8; j++) M = fmaxf(M, sm[j][lane]);
        float Zt = 0.f, At = 0.f;
        #pragma unroll
        for (int j = 0; j < 8; j++) {
            float c = __expf(sm[j][lane] - M);
            Zt += sz[j][lane] * c;
            At += sa[j][lane] * c;
        }
        out[base] = At / Zt;
    }
}

__global__ void pack_kernel(const float* __restrict__ ho, float* __restrict__ x0)
{
    const int i = blockIdx.x * blockDim.x + threadIdx.x;
    const int b = i >> 10;
    const int c = i & 1023;
    const int h = c >> 8;
    const int d = c & 255;
    x0[i] = ho[h * (BATCH * DIM) + b * DIM + d];
}

template<bool RELU, int K>
__global__ void smallgemm_kernel(const float* __restrict__ X, const float* __restrict__ Wt,
                                 const float* __restrict__ bias, float* __restrict__ C)
{
    __shared__ float Xs[32][257];
    __shared__ float Ws[8][257];
    const int tid = threadIdx.x;
    const int b  = tid & 31;
    const int nl = tid >> 5;
    const int n  = blockIdx.x * 8 + nl;
    float acc = 0.f;
    for (int k0 = 0; k0 < K; k0 += 256) {
        #pragma unroll
        for (int j = 0; j < 8; j++)
            Ws[j][tid] = Wt[(blockIdx.x * 8 + j) * K + k0 + tid];
        #pragma unroll
        for (int j = 0; j < 32; j++)
            Xs[j][tid] = X[j * K + k0 + tid];
        __syncthreads();
        #pragma unroll 8
        for (int kk = 0; kk < 256; kk++) acc += Xs[b][kk] * Ws[nl][kk];
        __syncthreads();
    }
    float val = acc + bias[n];
    if (RELU) val = fmaxf(val, 0.f);
    C[b * DIM + n] = val;
}

// ---------------------------------------------------------------------------
extern "C" void kernel_launch(void* const* d_in, const int* in_sizes, int n_in,
                              void* d_out, int out_size)
{
    const float* q   = (const float*)d_in[0];
    const float* k   = (const float*)d_in[1];
    const float* v   = (const float*)d_in[2];
    const float* wq  = (const float*)d_in[3];
    const float* bq  = (const float*)d_in[4];
    const float* wk  = (const float*)d_in[5];
    const float* bk  = (const float*)d_in[6];
    const float* wv  = (const float*)d_in[7];
    const float* bv  = (const float*)d_in[8];
    const float* g1  = (const float*)d_in[9];
    const float* be1 = (const float*)d_in[10];
    const float* wl1 = (const float*)d_in[11];
    const float* bl1 = (const float*)d_in[12];
    const float* g2  = (const float*)d_in[13];
    const float* be2 = (const float*)d_in[14];
    const float* wl2 = (const float*)d_in[15];
    const float* bl2 = (const float*)d_in[16];
    const float* mw0 = (const float*)d_in[17];
    const float* mb0 = (const float*)d_in[18];
    const float* mw1 = (const float*)d_in[19];
    const float* mb1 = (const float*)d_in[20];
    const float* mw2 = (const float*)d_in[21];
    const float* mb2 = (const float*)d_in[22];

    float* buf;   cudaGetSymbolAddress((void**)&buf,   g_buf);
    float* stats; cudaGetSymbolAddress((void**)&stats, g_stats);
    float* bnsc;  cudaGetSymbolAddress((void**)&bnsc,  g_bnscale);
    float* bnsh;  cudaGetSymbolAddress((void**)&bnsh,  g_bnshift);
    float* ho;    cudaGetSymbolAddress((void**)&ho,    g_headout);
    float* x0;    cudaGetSymbolAddress((void**)&x0,    g_x0);
    float* x1;    cudaGetSymbolAddress((void**)&x1,    g_x1);
    float* x2;    cudaGetSymbolAddress((void**)&x2,    g_x2);

    float* Qb[2] = { buf + (size_t)0*NBUF, buf + (size_t)1*NBUF };
    float* Kb[2] = { buf + (size_t)2*NBUF, buf + (size_t)3*NBUF };
    float* Vb[2] = { buf + (size_t)4*NBUF, buf + (size_t)5*NBUF };
    float* Wa    =   buf + (size_t)6*NBUF;
    float* Wb    =   buf + (size_t)7*NBUF;

    dim3 gg(DIM / 128, MROWS / 128);   // (2, 512)

    const float* Qc = q; const float* Kc = k; const float* Vc = v;
    for (int i = 0; i < HEADS; i++) {
        float* Qn = Qb[i & 1]; float* Kn = Kb[i & 1]; float* Vn = Vb[i & 1];

        mma_gemm_kernel<false><<<gg, 256>>>(Qc, wq + i*DIM*DIM, bq + i*DIM, nullptr, nullptr, Qn);
        mma_gemm_kernel<false><<<gg, 256>>>(Kc, wk + i*DIM*DIM, bk + i*DIM, nullptr, nullptr, Kn);
        mma_gemm_kernel<false><<<gg, 256>>>(Vc, wv + i*DIM*DIM, bv + i*DIM, nullptr, nullptr, Vn);

        zero_stats_kernel<<<1, 2*DIM>>>(stats);
        sub_stats_kernel<<<2048, DIM>>>(Kn, Qn, Wa, stats);
        bn_finalize_kernel<<<1, DIM>>>(stats, g1 + i*DIM, be1 + i*DIM, bnsc, bnsh);

        mma_gemm_kernel<true><<<gg, 256>>>(Wa, wl1 + i*DIM*DIM, bl1 + i*DIM, bnsc, bnsh, Wb);

        zero_stats_kernel<<<1, 2*DIM>>>(stats);
        stats_kernel<<<2048, DIM>>>(Wb, stats);
        bn_finalize_kernel<<<1, DIM>>>(stats, g2 + i*DIM, be2 + i*DIM, bnsc, bnsh);

        mma_gemm_kernel<true><<<gg, 256>>>(Wb, wl2 + i*DIM*DIM, bl2 + i*DIM, bnsc, bnsh, Wa);

        softmax_wsum_kernel<<<BATCH * (DIM / 32), 256>>>(Wa, Vn, ho + i*BATCH*DIM);

        Qc = Qn; Kc = Kn; Vc = Vn;
    }

    pack_kernel<<<32, 1024>>>(ho, x0);
    smallgemm_kernel<true,  HEADS*DIM><<<DIM / 8, 256>>>(x0, mw0, mb0, x1);
    smallgemm_kernel<true,  DIM      ><<<DIM / 8, 256>>>(x1, mw1, mb1, x2);
    smallgemm_kernel<false, DIM      ><<<DIM / 8, 256>>>(x2, mw2, mb2, (float*)d_out);
}